// round 1
// baseline (speedup 1.0000x reference)
#include <cuda_runtime.h>
#include <math.h>

#define S_GRID 14
#define B_BOX 2
#define C_CLS 20
#define NCH 30            // 5*B + C
#define CELLS_PER_BLOCK 128
#define THREADS 128
#define NB 4096
#define TOTAL_CELLS (NB * S_GRID * S_GRID)   // 802816

__device__ double g_acc;

__global__ void init_kernel() { g_acc = 0.0; }

__global__ void finalize_kernel(float* out) {
    out[0] = (float)(g_acc * (1.0 / (double)NB));
}

__device__ __forceinline__ float warp_reduce(float v) {
    #pragma unroll
    for (int o = 16; o > 0; o >>= 1) v += __shfl_down_sync(0xFFFFFFFFu, v, o);
    return v;
}

__global__ void __launch_bounds__(THREADS)
yolo_loss_kernel(const float* __restrict__ pred, const float* __restrict__ target) {
    __shared__ float sp[CELLS_PER_BLOCK * NCH];
    __shared__ float st[CELLS_PER_BLOCK * NCH];
    __shared__ float warp_sums[THREADS / 32];

    const int tid = threadIdx.x;
    const long long cell0 = (long long)blockIdx.x * CELLS_PER_BLOCK;

    // how many cells this block actually owns (last block guard; exact here but safe)
    int ncells = TOTAL_CELLS - (int)cell0;
    if (ncells > CELLS_PER_BLOCK) ncells = CELLS_PER_BLOCK;

    // cooperative coalesced stage: 128 cells * 30 ch = 3840 floats = 960 float4 each
    {
        const int nfloat4 = (ncells * NCH) / 4;   // NCH*128 divisible by 4
        const float4* gp = (const float4*)(pred + cell0 * NCH);
        const float4* gt = (const float4*)(target + cell0 * NCH);
        float4* s4p = (float4*)sp;
        float4* s4t = (float4*)st;
        for (int i = tid; i < nfloat4; i += THREADS) {
            s4p[i] = gp[i];
            s4t[i] = gt[i];
        }
    }
    __syncthreads();

    float cell_loss = 0.0f;
    if (tid < ncells) {
        const float* p = sp + tid * NCH;
        const float* t = st + tid * NCH;

        const float tconf = t[4];
        const float objm   = (tconf > 0.0f) ? 1.0f : 0.0f;
        const float noobjm = (tconf == 0.0f) ? 1.0f : 0.0f;

        // ---- no-object confidence loss (both box slots) ----
        float d0 = p[4] - t[4];
        float d1 = p[9] - t[9];
        float l_noobj = d0 * d0 + d1 * d1;

        // ---- IoU of each pred box vs target box 0 ----
        const float inv_s = 1.0f / (float)S_GRID;
        float tx = t[0] * inv_s, ty = t[1] * inv_s;
        float thw = 0.5f * t[2], thh = 0.5f * t[3];
        float tx0 = tx - thw, ty0 = ty - thh, tx1 = tx + thw, ty1 = ty + thh;
        float area_t = (tx1 - tx0) * (ty1 - ty0);

        float iou[B_BOX];
        #pragma unroll
        for (int b = 0; b < B_BOX; b++) {
            const float* pb = p + 5 * b;
            float px = pb[0] * inv_s, py = pb[1] * inv_s;
            float phw = 0.5f * pb[2], phh = 0.5f * pb[3];
            float px0 = px - phw, py0 = py - phh, px1 = px + phw, py1 = py + phh;
            float area_p = (px1 - px0) * (py1 - py0);
            float iw = fminf(px1, tx1) - fmaxf(px0, tx0);
            float ih = fminf(py1, ty1) - fmaxf(py0, ty0);
            iw = fmaxf(iw, 0.0f);
            ih = fmaxf(ih, 0.0f);
            float inter = iw * ih;
            iou[b] = inter / (area_p + area_t - inter);
        }

        // argmax, first-max on tie (jnp.argmax semantics)
        const int r = (iou[1] > iou[0]) ? 1 : 0;
        const float max_iou = fmaxf(iou[0], iou[1]);

        const float* pr = p + 5 * r;
        const float* tr = t + 5 * r;

        float dx = pr[0] - tr[0];
        float dy = pr[1] - tr[1];
        float l_xy = dx * dx + dy * dy;

        float dw = sqrtf(pr[2]) - sqrtf(tr[2]);
        float dh = sqrtf(pr[3]) - sqrtf(tr[3]);
        float l_wh = dw * dw + dh * dh;

        float dob = pr[4] - max_iou;
        float l_obj = dob * dob;

        float l_cls = 0.0f;
        #pragma unroll
        for (int c = 0; c < C_CLS; c++) {
            float dc = p[10 + c] - t[10 + c];
            l_cls = fmaf(dc, dc, l_cls);
        }

        cell_loss = objm * (5.0f * (l_xy + l_wh) + l_obj + l_cls)
                  + 0.5f * noobjm * l_noobj;
    }

    // ---- block reduction ----
    float v = warp_reduce(cell_loss);
    const int lane = tid & 31;
    const int wid = tid >> 5;
    if (lane == 0) warp_sums[wid] = v;
    __syncthreads();
    if (wid == 0) {
        float s = (lane < THREADS / 32) ? warp_sums[lane] : 0.0f;
        #pragma unroll
        for (int o = (THREADS / 64); o > 0; o >>= 1) s += __shfl_down_sync(0xFFFFFFFFu, s, o);
        if (lane == 0) atomicAdd(&g_acc, (double)s);
    }
}

extern "C" void kernel_launch(void* const* d_in, const int* in_sizes, int n_in,
                              void* d_out, int out_size) {
    const float* pred = (const float*)d_in[0];
    const float* target = (const float*)d_in[1];
    float* out = (float*)d_out;

    init_kernel<<<1, 1>>>();
    const int nblocks = (TOTAL_CELLS + CELLS_PER_BLOCK - 1) / CELLS_PER_BLOCK; // 6272
    yolo_loss_kernel<<<nblocks, THREADS>>>(pred, target);
    finalize_kernel<<<1, 1>>>(out);
}

// round 2
// speedup vs baseline: 1.0307x; 1.0307x over previous
#include <cuda_runtime.h>
#include <math.h>

#define S_GRID 14
#define B_BOX 2
#define C_CLS 20
#define NCH 30            // 5*B + C
#define CELLS_PER_BLOCK 128
#define THREADS 128
#define NB 4096
#define TOTAL_CELLS (NB * S_GRID * S_GRID)   // 802816, divisible by 128
#define NBLOCKS (TOTAL_CELLS / CELLS_PER_BLOCK) // 6272

__device__ double g_acc = 0.0;
__device__ unsigned int g_ticket = 0u;

__device__ __forceinline__ float warp_reduce(float v) {
    #pragma unroll
    for (int o = 16; o > 0; o >>= 1) v += __shfl_down_sync(0xFFFFFFFFu, v, o);
    return v;
}

__global__ void __launch_bounds__(THREADS)
yolo_loss_kernel(const float* __restrict__ pred, const float* __restrict__ target,
                 float* __restrict__ out) {
    __shared__ float sp[CELLS_PER_BLOCK * NCH];
    __shared__ float st[CELLS_PER_BLOCK * NCH];
    __shared__ float warp_sums[THREADS / 32];

    const int tid = threadIdx.x;
    const long long cell0 = (long long)blockIdx.x * CELLS_PER_BLOCK;

    // cooperative coalesced stage: 128 cells * 30 ch = 3840 floats = 960 float4 per array
    {
        const float4* __restrict__ gp = (const float4*)(pred + cell0 * NCH);
        const float4* __restrict__ gt = (const float4*)(target + cell0 * NCH);
        float4* s4p = (float4*)sp;
        float4* s4t = (float4*)st;
        // 960 float4 / 128 threads = 7.5 -> do 8 strides with bound check on last
        #pragma unroll
        for (int k = 0; k < 7; k++) {
            const int i = tid + k * THREADS;
            s4p[i] = gp[i];
            s4t[i] = gt[i];
        }
        {
            const int i = tid + 7 * THREADS;
            if (i < (CELLS_PER_BLOCK * NCH) / 4) { s4p[i] = gp[i]; s4t[i] = gt[i]; }
        }
    }
    __syncthreads();

    float cell_loss;
    {
        const float* p = sp + tid * NCH;
        const float* t = st + tid * NCH;

        const float tconf = t[4];
        const float objm   = (tconf > 0.0f) ? 1.0f : 0.0f;
        const float noobjm = (tconf == 0.0f) ? 1.0f : 0.0f;

        // ---- no-object confidence loss (both box slots) ----
        float d0 = p[4] - t[4];
        float d1 = p[9] - t[9];
        float l_noobj = d0 * d0 + d1 * d1;

        // ---- IoU of each pred box vs target box 0 ----
        const float inv_s = 1.0f / (float)S_GRID;
        float tx = t[0] * inv_s, ty = t[1] * inv_s;
        float thw = 0.5f * t[2], thh = 0.5f * t[3];
        float tx0 = tx - thw, ty0 = ty - thh, tx1 = tx + thw, ty1 = ty + thh;
        float area_t = (tx1 - tx0) * (ty1 - ty0);

        float iou[B_BOX];
        #pragma unroll
        for (int b = 0; b < B_BOX; b++) {
            const float* pb = p + 5 * b;
            float px = pb[0] * inv_s, py = pb[1] * inv_s;
            float phw = 0.5f * pb[2], phh = 0.5f * pb[3];
            float px0 = px - phw, py0 = py - phh, px1 = px + phw, py1 = py + phh;
            float area_p = (px1 - px0) * (py1 - py0);
            float iw = fminf(px1, tx1) - fmaxf(px0, tx0);
            float ih = fminf(py1, ty1) - fmaxf(py0, ty0);
            iw = fmaxf(iw, 0.0f);
            ih = fmaxf(ih, 0.0f);
            float inter = iw * ih;
            iou[b] = inter / (area_p + area_t - inter);
        }

        // argmax, first-max on tie (jnp.argmax semantics)
        const int r = (iou[1] > iou[0]) ? 1 : 0;
        const float max_iou = fmaxf(iou[0], iou[1]);

        const float* pr = p + 5 * r;
        const float* tr = t + 5 * r;

        float dx = pr[0] - tr[0];
        float dy = pr[1] - tr[1];
        float l_xy = dx * dx + dy * dy;

        float dw = sqrtf(pr[2]) - sqrtf(tr[2]);
        float dh = sqrtf(pr[3]) - sqrtf(tr[3]);
        float l_wh = dw * dw + dh * dh;

        float dob = pr[4] - max_iou;
        float l_obj = dob * dob;

        float l_cls = 0.0f;
        #pragma unroll
        for (int c = 0; c < C_CLS; c++) {
            float dc = p[10 + c] - t[10 + c];
            l_cls = fmaf(dc, dc, l_cls);
        }

        cell_loss = objm * (5.0f * (l_xy + l_wh) + l_obj + l_cls)
                  + 0.5f * noobjm * l_noobj;
    }

    // ---- block reduction ----
    float v = warp_reduce(cell_loss);
    const int lane = tid & 31;
    const int wid = tid >> 5;
    if (lane == 0) warp_sums[wid] = v;
    __syncthreads();

    if (tid == 0) {
        float s = warp_sums[0] + warp_sums[1] + warp_sums[2] + warp_sums[3];
        atomicAdd(&g_acc, (double)s);
        __threadfence();
        unsigned int ticket = atomicAdd(&g_ticket, 1u);
        if (ticket == (unsigned int)(NBLOCKS - 1)) {
            // last block: all prior g_acc adds are visible (fence + atomic order on same L2 line)
            double total = g_acc;
            out[0] = (float)(total * (1.0 / (double)NB));
            // reset for next graph replay (deterministic across replays)
            g_acc = 0.0;
            __threadfence();
            g_ticket = 0u;
        }
    }
}

extern "C" void kernel_launch(void* const* d_in, const int* in_sizes, int n_in,
                              void* d_out, int out_size) {
    const float* pred = (const float*)d_in[0];
    const float* target = (const float*)d_in[1];
    float* out = (float*)d_out;
    yolo_loss_kernel<<<NBLOCKS, THREADS>>>(pred, target, out);
}

// round 3
// speedup vs baseline: 1.2691x; 1.2313x over previous
#include <cuda_runtime.h>
#include <math.h>

#define NCH 30
#define CPB 128       // cells per block
#define THREADS 128
#define NB 4096
#define TOTAL_CELLS (NB * 14 * 14)          // 802816
#define NBLOCKS (TOTAL_CELLS / CPB)         // 6272
#define F2_PER_BLOCK (CPB * 15)             // 1920 float2 per array

__device__ double g_acc = 0.0;
__device__ unsigned int g_ticket = 0u;

__global__ void __launch_bounds__(THREADS, 9)
yolo_loss_kernel(const float* __restrict__ pred, const float* __restrict__ target,
                 float* __restrict__ out) {
    __shared__ float2 sbp[CPB * 5];    // pred  box channels 0..9 (raw)
    __shared__ float2 sbt[CPB * 5];    // target box channels 0..9 (raw)
    __shared__ float  scls[CPB * 10];  // per (cell, class-pair) squared diff
    __shared__ float  warp_sums[THREADS / 32];

    const int tid = threadIdx.x;
    const long long base = (long long)blockIdx.x * F2_PER_BLOCK;
    const float2* __restrict__ gp = (const float2*)pred + base;
    const float2* __restrict__ gt = (const float2*)target + base;

    // staging: 15 float2 per thread per array; exact (1920 = 15*128), no tail
    #pragma unroll
    for (int k = 0; k < 15; k++) {
        const int g = tid + k * THREADS;
        const int cell = g / 15;
        const int j = g - cell * 15;          // float2 slot within cell: ch 2j,2j+1
        const float2 p = __ldcs(gp + g);
        const float2 t = __ldcs(gt + g);
        if (j < 5) {
            sbp[cell * 5 + j] = p;
            sbt[cell * 5 + j] = t;
        } else {
            const float dx = p.x - t.x;
            const float dy = p.y - t.y;
            scls[cell * 10 + (j - 5)] = dx * dx + dy * dy;
        }
    }
    __syncthreads();

    float cell_loss;
    {
        const float2* pb = sbp + tid * 5;
        const float2* tb = sbt + tid * 5;
        const float2 pb0 = pb[0], pb1 = pb[1], pb2 = pb[2], pb3 = pb[3], pb4 = pb[4];
        const float2 tb0 = tb[0], tb1 = tb[1], tb2 = tb[2], tb3 = tb[3], tb4 = tb[4];

        const float p0 = pb0.x, p1 = pb0.y, p2 = pb1.x, p3 = pb1.y, p4 = pb2.x;
        const float p5 = pb2.y, p6 = pb3.x, p7 = pb3.y, p8 = pb4.x, p9 = pb4.y;
        const float t0 = tb0.x, t1 = tb0.y, t2 = tb1.x, t3 = tb1.y, t4 = tb2.x;
        const float t5 = tb2.y, t6 = tb3.x, t7 = tb3.y, t8 = tb4.x, t9 = tb4.y;

        const float objm   = (t4 > 0.0f) ? 1.0f : 0.0f;
        const float noobjm = (t4 == 0.0f) ? 1.0f : 0.0f;

        // no-object confidence loss (both box slots)
        const float d4 = p4 - t4, d9 = p9 - t9;
        const float l_noobj = d4 * d4 + d9 * d9;

        // target box 0 corners
        const float inv_s = 1.0f / 14.0f;
        const float txc = t0 * inv_s, tyc = t1 * inv_s;
        const float thw = 0.5f * t2, thh = 0.5f * t3;
        const float tx0 = txc - thw, ty0 = tyc - thh, tx1 = txc + thw, ty1 = tyc + thh;
        const float area_t = (tx1 - tx0) * (ty1 - ty0);

        // IoU box 0
        float iou0, iou1;
        {
            const float pxc = p0 * inv_s, pyc = p1 * inv_s;
            const float phw = 0.5f * p2, phh = 0.5f * p3;
            const float px0 = pxc - phw, py0 = pyc - phh, px1 = pxc + phw, py1 = pyc + phh;
            const float area_p = (px1 - px0) * (py1 - py0);
            const float iw = fmaxf(fminf(px1, tx1) - fmaxf(px0, tx0), 0.0f);
            const float ih = fmaxf(fminf(py1, ty1) - fmaxf(py0, ty0), 0.0f);
            const float inter = iw * ih;
            iou0 = inter / (area_p + area_t - inter);
        }
        // IoU box 1
        {
            const float pxc = p5 * inv_s, pyc = p6 * inv_s;
            const float phw = 0.5f * p7, phh = 0.5f * p8;
            const float px0 = pxc - phw, py0 = pyc - phh, px1 = pxc + phw, py1 = pyc + phh;
            const float area_p = (px1 - px0) * (py1 - py0);
            const float iw = fmaxf(fminf(px1, tx1) - fmaxf(px0, tx0), 0.0f);
            const float ih = fmaxf(fminf(py1, ty1) - fmaxf(py0, ty0), 0.0f);
            const float inter = iw * ih;
            iou1 = inter / (area_p + area_t - inter);
        }

        // responsible box: first-max on tie (jnp.argmax semantics)
        const bool r1 = (iou1 > iou0);
        const float max_iou = fmaxf(iou0, iou1);

        const float prx = r1 ? p5 : p0,  pry = r1 ? p6 : p1;
        const float prw = r1 ? p7 : p2,  prh = r1 ? p8 : p3;
        const float prc = r1 ? p9 : p4;
        const float trx = r1 ? t5 : t0,  try_ = r1 ? t6 : t1;
        const float trw = r1 ? t7 : t2,  trh = r1 ? t8 : t3;

        const float dx = prx - trx, dy = pry - try_;
        const float l_xy = dx * dx + dy * dy;

        const float dw = sqrtf(prw) - sqrtf(trw);
        const float dh = sqrtf(prh) - sqrtf(trh);
        const float l_wh = dw * dw + dh * dh;

        const float dob = prc - max_iou;
        const float l_obj = dob * dob;

        // class loss: precomputed pair-SSEs in smem
        const float* sc = scls + tid * 10;
        float l_cls = 0.0f;
        #pragma unroll
        for (int i = 0; i < 10; i++) l_cls += sc[i];

        cell_loss = objm * (5.0f * (l_xy + l_wh) + l_obj + l_cls)
                  + 0.5f * noobjm * l_noobj;
    }

    // block reduction
    float v = cell_loss;
    #pragma unroll
    for (int o = 16; o > 0; o >>= 1) v += __shfl_down_sync(0xFFFFFFFFu, v, o);
    const int lane = tid & 31;
    const int wid = tid >> 5;
    if (lane == 0) warp_sums[wid] = v;
    __syncthreads();

    if (tid == 0) {
        const float s = warp_sums[0] + warp_sums[1] + warp_sums[2] + warp_sums[3];
        atomicAdd(&g_acc, (double)s);
        __threadfence();
        const unsigned int ticket = atomicAdd(&g_ticket, 1u);
        if (ticket == (unsigned int)(NBLOCKS - 1)) {
            const double total = g_acc;
            out[0] = (float)(total * (1.0 / (double)NB));
            g_acc = 0.0;           // reset for next graph replay
            __threadfence();
            g_ticket = 0u;
        }
    }
}

extern "C" void kernel_launch(void* const* d_in, const int* in_sizes, int n_in,
                              void* d_out, int out_size) {
    const float* pred = (const float*)d_in[0];
    const float* target = (const float*)d_in[1];
    float* out = (float*)d_out;
    yolo_loss_kernel<<<NBLOCKS, THREADS>>>(pred, target, out);
}

// round 4
// speedup vs baseline: 1.2772x; 1.0063x over previous
#include <cuda_runtime.h>
#include <stdint.h>
#include <math.h>

#define THREADS 64
#define CPT 64                        // cells per tile (= threads, 1 cell/thread)
#define NB 4096
#define TOTAL_CELLS (NB * 14 * 14)    // 802816
#define NTILES (TOTAL_CELLS / CPT)    // 12544
#define GRID (148 * 7)                // 1036 persistent blocks, one wave
#define TILE_F4 (CPT * 30 / 4)        // 480 float4 per array per tile

__device__ double g_acc = 0.0;
__device__ unsigned int g_ticket = 0u;

__device__ __forceinline__ void cp16(uint32_t s, const float4* g) {
    asm volatile("cp.async.cg.shared.global [%0], [%1], 16;" :: "r"(s), "l"(g));
}
__device__ __forceinline__ void cp_commit() {
    asm volatile("cp.async.commit_group;" ::: "memory");
}

__global__ void __launch_bounds__(THREADS)
yolo_loss_kernel(const float* __restrict__ pred, const float* __restrict__ target,
                 float* __restrict__ out) {
    __shared__ float sp[2][CPT * 30];
    __shared__ float st[2][CPT * 30];
    __shared__ float wsum[2];

    const int tid = threadIdx.x;
    const uint32_t sp0 = (uint32_t)__cvta_generic_to_shared(&sp[0][0]);
    const uint32_t st0 = (uint32_t)__cvta_generic_to_shared(&st[0][0]);
    const uint32_t buf_stride = (uint32_t)(CPT * 30 * sizeof(float));

    // ---- issue loads for a tile into buffer b ----
    auto issue = [&](int tile, int b) {
        const float4* gp = (const float4*)pred + (size_t)tile * TILE_F4;
        const float4* gt = (const float4*)target + (size_t)tile * TILE_F4;
        const uint32_t dp = sp0 + (uint32_t)b * buf_stride;
        const uint32_t dt = st0 + (uint32_t)b * buf_stride;
        #pragma unroll
        for (int k = 0; k < 7; k++) {
            const int i = tid + k * THREADS;
            cp16(dp + i * 16, gp + i);
            cp16(dt + i * 16, gt + i);
        }
        {   // 480 = 7*64 + 32: tail for half the threads
            const int i = tid + 7 * THREADS;
            if (i < TILE_F4) { cp16(dp + i * 16, gp + i); cp16(dt + i * 16, gt + i); }
        }
    };

    float acc = 0.0f;
    int t = blockIdx.x;               // GRID <= NTILES, so always valid initially
    issue(t, 0);
    cp_commit();
    int b = 0;

    while (t < NTILES) {
        const int tn = t + GRID;
        if (tn < NTILES) {
            issue(tn, b ^ 1);
            cp_commit();
            asm volatile("cp.async.wait_group 1;" ::: "memory");
        } else {
            cp_commit();              // empty group, keeps accounting simple
            asm volatile("cp.async.wait_group 0;" ::: "memory");
        }
        __syncthreads();              // tile t visible in buffer b to all threads

        // ---- per-cell loss from smem ----
        {
            const float* p = &sp[b][tid * 30];
            const float* tt = &st[b][tid * 30];

            const float t4 = tt[4];
            const float objm   = (t4 > 0.0f) ? 1.0f : 0.0f;
            const float noobjm = (t4 == 0.0f) ? 1.0f : 0.0f;

            // no-object confidence loss (both box slots)
            const float d4 = p[4] - t4;
            const float d9 = p[9] - tt[9];
            const float l_noobj = d4 * d4 + d9 * d9;

            // target box 0 corners
            const float inv_s = 1.0f / 14.0f;
            const float txc = tt[0] * inv_s, tyc = tt[1] * inv_s;
            const float thw = 0.5f * tt[2], thh = 0.5f * tt[3];
            const float tx0 = txc - thw, ty0 = tyc - thh;
            const float tx1 = txc + thw, ty1 = tyc + thh;
            const float area_t = (tx1 - tx0) * (ty1 - ty0);

            float iou[2];
            #pragma unroll
            for (int bb = 0; bb < 2; bb++) {
                const float* pb = p + 5 * bb;
                const float pxc = pb[0] * inv_s, pyc = pb[1] * inv_s;
                const float phw = 0.5f * pb[2], phh = 0.5f * pb[3];
                const float px0 = pxc - phw, py0 = pyc - phh;
                const float px1 = pxc + phw, py1 = pyc + phh;
                const float area_p = (px1 - px0) * (py1 - py0);
                const float iw = fmaxf(fminf(px1, tx1) - fmaxf(px0, tx0), 0.0f);
                const float ih = fmaxf(fminf(py1, ty1) - fmaxf(py0, ty0), 0.0f);
                const float inter = iw * ih;
                iou[bb] = inter / (area_p + area_t - inter);
            }

            // responsible box: first-max on tie (jnp.argmax semantics)
            const int roff = (iou[1] > iou[0]) ? 5 : 0;
            const float max_iou = fmaxf(iou[0], iou[1]);

            const float* pr = p + roff;
            const float* tr = tt + roff;

            const float dx = pr[0] - tr[0];
            const float dy = pr[1] - tr[1];
            const float l_xy = dx * dx + dy * dy;

            const float dw = sqrtf(pr[2]) - sqrtf(tr[2]);
            const float dh = sqrtf(pr[3]) - sqrtf(tr[3]);
            const float l_wh = dw * dw + dh * dh;

            const float dob = pr[4] - max_iou;
            const float l_obj = dob * dob;

            float l_cls = 0.0f;
            #pragma unroll
            for (int c = 0; c < 20; c++) {
                const float dc = p[10 + c] - tt[10 + c];
                l_cls = fmaf(dc, dc, l_cls);
            }

            acc += objm * (5.0f * (l_xy + l_wh) + l_obj + l_cls)
                 + 0.5f * noobjm * l_noobj;
        }

        __syncthreads();              // everyone done reading buf b before next overwrite
        b ^= 1;
        t = tn;
    }

    // ---- block reduction (2 warps) + global accumulate ----
    float v = acc;
    #pragma unroll
    for (int o = 16; o > 0; o >>= 1) v += __shfl_down_sync(0xFFFFFFFFu, v, o);
    if ((tid & 31) == 0) wsum[tid >> 5] = v;
    __syncthreads();

    if (tid == 0) {
        const float s = wsum[0] + wsum[1];
        atomicAdd(&g_acc, (double)s);
        __threadfence();
        const unsigned int ticket = atomicAdd(&g_ticket, 1u);
        if (ticket == (unsigned int)(GRID - 1)) {
            const double total = g_acc;
            out[0] = (float)(total * (1.0 / (double)NB));
            g_acc = 0.0;              // reset for next graph replay
            __threadfence();
            g_ticket = 0u;
        }
    }
}

extern "C" void kernel_launch(void* const* d_in, const int* in_sizes, int n_in,
                              void* d_out, int out_size) {
    const float* pred = (const float*)d_in[0];
    const float* target = (const float*)d_in[1];
    float* out = (float*)d_out;
    yolo_loss_kernel<<<GRID, THREADS>>>(pred, target, out);
}